// round 7
// baseline (speedup 1.0000x reference)
#include <cuda_runtime.h>
#include <math.h>
#include <stdint.h>

#define NLEV 16
#define TBL (1u << 19)
#define NMAX (1 << 20)

struct LevelP {
    float scale[NLEV];
    uint32_t res[NLEV];
    uint32_t dense_mask;
};

// Planar float4 scratch for h[16] per point: 4 planes x 16 MB = 64 MB.
__device__ float4 g_h0[NMAX];
__device__ float4 g_h1[NMAX];
__device__ float4 g_h2[NMAX];
__device__ float4 g_h3[NMAX];

// ============================ Kernel 1: encode + h + sigma/uncert ==========
__global__ __launch_bounds__(256, 2)
void ngp_encode_kernel(const float* __restrict__ gx,
                       const float* __restrict__ table,
                       const float* __restrict__ w1,
                       const float* __restrict__ w2,
                       const float* __restrict__ wa1,
                       const float* __restrict__ wa2,
                       const float* __restrict__ wu1,
                       const float* __restrict__ wu2,
                       float* __restrict__ out,
                       int N, LevelP lp)
{
    __shared__ __align__(16) float s_w1T[64 * 32];   // [out j][in i]
    __shared__ __align__(16) float s_w2[64 * 16];    // row-major
    __shared__ __align__(16) float s_wa1T[32 * 16];
    __shared__ __align__(16) float s_wa2[32];
    __shared__ __align__(16) float s_wuf[16];        // folded wu1@wu2

    for (int t = threadIdx.x; t < 64 * 32; t += 256) {
        int j = t >> 5, i = t & 31;
        s_w1T[t] = w1[i * 64 + j];
    }
    for (int t = threadIdx.x; t < 64 * 16; t += 256) s_w2[t] = w2[t];
    for (int t = threadIdx.x; t < 32 * 16; t += 256) {
        int j = t >> 4, i = t & 15;
        s_wa1T[t] = wa1[i * 32 + j];
    }
    if (threadIdx.x < 32) s_wa2[threadIdx.x] = wa2[threadIdx.x];
    if (threadIdx.x < 16) {
        float acc = 0.0f;
        for (int j = 0; j < 32; j++)
            acc = fmaf(wu1[threadIdx.x * 32 + j], wu2[j], acc);
        s_wuf[threadIdx.x] = acc;
    }
    __syncthreads();

    int i0 = blockIdx.x * blockDim.x + threadIdx.x;
    if (i0 >= N) return;

    // x01 = (x + 1) * 0.5 -- exact rounded ops (floor-sensitive path)
    float px = __fmul_rn(__fadd_rn(gx[3 * i0 + 0], 1.0f), 0.5f);
    float py = __fmul_rn(__fadd_rn(gx[3 * i0 + 1], 1.0f), 0.5f);
    float pz = __fmul_rn(__fadd_rn(gx[3 * i0 + 2], 1.0f), 0.5f);

    // ---------------- grid encode: 16 levels x 8 corners x float2 ------------
    float enc[32];
    #pragma unroll
    for (int l = 0; l < NLEV; l++) {
        const float s = lp.scale[l];
        const uint32_t res = lp.res[l];
        const bool dense = (lp.dense_mask >> l) & 1u;

        float posx = __fadd_rn(__fmul_rn(px, s), 0.5f);
        float posy = __fadd_rn(__fmul_rn(py, s), 0.5f);
        float posz = __fadd_rn(__fmul_rn(pz, s), 0.5f);
        float gxf = floorf(posx), gyf = floorf(posy), gzf = floorf(posz);
        float fx = posx - gxf, fy = posy - gyf, fz = posz - gzf;
        uint32_t X = (uint32_t)gxf, Y = (uint32_t)gyf, Z = (uint32_t)gzf;

        const float2* tab = (const float2*)table + (size_t)l * TBL;

        uint32_t hy0 = Y * 2654435761u;
        uint32_t hy1 = (Y + 1u) * 2654435761u;
        uint32_t hz0 = Z * 805459861u;
        uint32_t hz1 = (Z + 1u) * 805459861u;
        uint32_t dy0 = Y * res,        dy1 = (Y + 1u) * res;
        uint32_t dz0 = Z * res * res,  dz1 = (Z + 1u) * res * res;

        float wx1 = fx, wx0 = 1.0f - fx;
        float wy1 = fy, wy0 = 1.0f - fy;
        float wz1 = fz, wz0 = 1.0f - fz;

        float e0 = 0.0f, e1 = 0.0f;
        #pragma unroll
        for (int c = 0; c < 8; c++) {
            const uint32_t bi = (c >> 2) & 1, bj = (c >> 1) & 1, bk = c & 1;
            uint32_t cx = X + bi;
            uint32_t idx;
            if (dense) {
                idx = cx + (bj ? dy1 : dy0) + (bk ? dz1 : dz0);
            } else {
                idx = (cx ^ (bj ? hy1 : hy0) ^ (bk ? hz1 : hz0)) & (TBL - 1u);
            }
            float w = (bi ? wx1 : wx0) * (bj ? wy1 : wy0) * (bk ? wz1 : wz0);
            float2 f = __ldg(tab + idx);
            e0 = fmaf(f.x, w, e0);
            e1 = fmaf(f.y, w, e1);
        }
        enc[2 * l + 0] = e0;
        enc[2 * l + 1] = e1;
    }

    // ---------------- h = relu(enc @ w1) @ w2 (streamed) ---------------------
    float h[16];
    #pragma unroll
    for (int k = 0; k < 16; k++) h[k] = 0.0f;
    for (int j = 0; j < 64; j++) {
        const float4* wr = (const float4*)&s_w1T[j * 32];
        float acc = 0.0f;
        #pragma unroll
        for (int q = 0; q < 8; q++) {
            float4 w4 = wr[q];
            acc = fmaf(enc[4 * q + 0], w4.x, acc);
            acc = fmaf(enc[4 * q + 1], w4.y, acc);
            acc = fmaf(enc[4 * q + 2], w4.z, acc);
            acc = fmaf(enc[4 * q + 3], w4.w, acc);
        }
        float t1 = fmaxf(acc, 0.0f);
        const float4* w2r = (const float4*)&s_w2[j * 16];
        #pragma unroll
        for (int q = 0; q < 4; q++) {
            float4 w4 = w2r[q];
            h[4 * q + 0] = fmaf(t1, w4.x, h[4 * q + 0]);
            h[4 * q + 1] = fmaf(t1, w4.y, h[4 * q + 1]);
            h[4 * q + 2] = fmaf(t1, w4.z, h[4 * q + 2]);
            h[4 * q + 3] = fmaf(t1, w4.w, h[4 * q + 3]);
        }
    }

    // ---------------- sigma head: relu(h@wa1)@wa2 ----------------------------
    float sacc = 0.0f;
    for (int j = 0; j < 32; j++) {
        const float4* wa = (const float4*)&s_wa1T[j * 16];
        float a = 0.0f;
        #pragma unroll
        for (int q = 0; q < 4; q++) {
            float4 a4 = wa[q];
            a = fmaf(h[4 * q + 0], a4.x, a);
            a = fmaf(h[4 * q + 1], a4.y, a);
            a = fmaf(h[4 * q + 2], a4.z, a);
            a = fmaf(h[4 * q + 3], a4.w, a);
        }
        sacc = fmaf(fmaxf(a, 0.0f), s_wa2[j], sacc);
    }

    // ---------------- uncert head: h @ folded --------------------------------
    float uacc = 0.0f;
    #pragma unroll
    for (int q = 0; q < 4; q++) {
        float4 w4 = ((const float4*)s_wuf)[q];
        uacc = fmaf(h[4 * q + 0], w4.x, uacc);
        uacc = fmaf(h[4 * q + 1], w4.y, uacc);
        uacc = fmaf(h[4 * q + 2], w4.z, uacc);
        uacc = fmaf(h[4 * q + 3], w4.w, uacc);
    }

    out[i0] = __expf(sacc);
    out[4 * N + i0] = __expf(uacc);

    // ---------------- stage h planar (coalesced float4 stores) ---------------
    g_h0[i0] = make_float4(h[0],  h[1],  h[2],  h[3]);
    g_h1[i0] = make_float4(h[4],  h[5],  h[6],  h[7]);
    g_h2[i0] = make_float4(h[8],  h[9],  h[10], h[11]);
    g_h3[i0] = make_float4(h[12], h[13], h[14], h[15]);
}

// ============================ Kernel 2: SH + render MLP + rgb ===============
__global__ __launch_bounds__(256, 2)
void ngp_render_kernel(const float* __restrict__ gd,
                       const float* __restrict__ wr1,
                       const float* __restrict__ wr2,
                       const float* __restrict__ wr3,
                       float* __restrict__ out,
                       int N)
{
    __shared__ __align__(16) float s_wr1T[64 * 32];
    __shared__ __align__(16) float s_wr2T[64 * 64];
    __shared__ __align__(16) float s_wr3p[64 * 4];   // padded -> LDS.128

    for (int t = threadIdx.x; t < 64 * 32; t += 256) {
        int j = t >> 5, i = t & 31;
        s_wr1T[t] = wr1[i * 64 + j];
    }
    for (int t = threadIdx.x; t < 64 * 64; t += 256) {
        int j = t >> 6, i = t & 63;
        s_wr2T[t] = wr2[i * 64 + j];
    }
    for (int t = threadIdx.x; t < 64; t += 256) {
        s_wr3p[t * 4 + 0] = wr3[t * 3 + 0];
        s_wr3p[t * 4 + 1] = wr3[t * 3 + 1];
        s_wr3p[t * 4 + 2] = wr3[t * 3 + 2];
        s_wr3p[t * 4 + 3] = 0.0f;
    }
    __syncthreads();

    int i0 = blockIdx.x * blockDim.x + threadIdx.x;
    if (i0 >= N) return;

    // load h (coalesced planar float4)
    float h[16];
    {
        float4 v;
        v = g_h0[i0]; h[0]=v.x;  h[1]=v.y;  h[2]=v.z;  h[3]=v.w;
        v = g_h1[i0]; h[4]=v.x;  h[5]=v.y;  h[6]=v.z;  h[7]=v.w;
        v = g_h2[i0]; h[8]=v.x;  h[9]=v.y;  h[10]=v.z; h[11]=v.w;
        v = g_h3[i0]; h[12]=v.x; h[13]=v.y; h[14]=v.z; h[15]=v.w;
    }

    // ---------------- spherical harmonics (deg 4) ----------------------------
    float vx = __fadd_rn(__fadd_rn(gd[3 * i0 + 0], 1.0f), -1.0f);
    float vy = __fadd_rn(__fadd_rn(gd[3 * i0 + 1], 1.0f), -1.0f);
    float vz = __fadd_rn(__fadd_rn(gd[3 * i0 + 2], 1.0f), -1.0f);
    float x2 = vx * vx, y2 = vy * vy, z2 = vz * vz;
    float xy = vx * vy, yz = vy * vz, xz = vx * vz;
    float sh[16];
    sh[0]  = 0.28209479177387814f;
    sh[1]  = -0.48860251190291987f * vy;
    sh[2]  = 0.48860251190291987f * vz;
    sh[3]  = -0.48860251190291987f * vx;
    sh[4]  = 1.0925484305920792f * xy;
    sh[5]  = -1.0925484305920792f * yz;
    sh[6]  = 0.94617469575756f * z2 - 0.31539156525252f;
    sh[7]  = -1.0925484305920792f * xz;
    sh[8]  = 0.5462742152960396f * (x2 - y2);
    sh[9]  = 0.5900435899266435f * vy * (-3.0f * x2 + y2);
    sh[10] = 2.890611442640554f * xy * vz;
    sh[11] = 0.4570457994644657f * vy * (1.0f - 5.0f * z2);
    sh[12] = 0.3731763325901154f * vz * (5.0f * z2 - 3.0f);
    sh[13] = 0.4570457994644657f * vx * (1.0f - 5.0f * z2);
    sh[14] = 1.445305721320277f * vz * (x2 - y2);
    sh[15] = 0.5900435899266435f * vx * (-x2 + 3.0f * y2);

    // ---------------- z1 = relu([sh, h] @ wr1) -------------------------------
    float z1[64];
    #pragma unroll
    for (int j = 0; j < 64; j++) {
        const float4* wr = (const float4*)&s_wr1T[j * 32];
        float acc = 0.0f;
        #pragma unroll
        for (int q = 0; q < 4; q++) {
            float4 w4 = wr[q];
            acc = fmaf(sh[4 * q + 0], w4.x, acc);
            acc = fmaf(sh[4 * q + 1], w4.y, acc);
            acc = fmaf(sh[4 * q + 2], w4.z, acc);
            acc = fmaf(sh[4 * q + 3], w4.w, acc);
        }
        #pragma unroll
        for (int q = 0; q < 4; q++) {
            float4 w4 = wr[4 + q];
            acc = fmaf(h[4 * q + 0], w4.x, acc);
            acc = fmaf(h[4 * q + 1], w4.y, acc);
            acc = fmaf(h[4 * q + 2], w4.z, acc);
            acc = fmaf(h[4 * q + 3], w4.w, acc);
        }
        z1[j] = fmaxf(acc, 0.0f);
    }

    // ---------------- rgb = sigmoid(relu(z1 @ wr2) @ wr3) --------------------
    float r0 = 0.0f, r1 = 0.0f, r2 = 0.0f;
    for (int j = 0; j < 64; j++) {
        const float4* wr = (const float4*)&s_wr2T[j * 64];
        float acc = 0.0f;
        #pragma unroll
        for (int q = 0; q < 16; q++) {
            float4 w4 = wr[q];
            acc = fmaf(z1[4 * q + 0], w4.x, acc);
            acc = fmaf(z1[4 * q + 1], w4.y, acc);
            acc = fmaf(z1[4 * q + 2], w4.z, acc);
            acc = fmaf(z1[4 * q + 3], w4.w, acc);
        }
        float z = fmaxf(acc, 0.0f);
        float4 w3 = ((const float4*)s_wr3p)[j];
        r0 = fmaf(z, w3.x, r0);
        r1 = fmaf(z, w3.y, r1);
        r2 = fmaf(z, w3.z, r2);
    }

    out[N + 3 * i0 + 0] = __fdividef(1.0f, 1.0f + __expf(-r0));
    out[N + 3 * i0 + 1] = __fdividef(1.0f, 1.0f + __expf(-r1));
    out[N + 3 * i0 + 2] = __fdividef(1.0f, 1.0f + __expf(-r2));
}

extern "C" void kernel_launch(void* const* d_in, const int* in_sizes, int n_in,
                              void* d_out, int out_size) {
    const float* x     = (const float*)d_in[0];
    const float* d     = (const float*)d_in[1];
    const float* table = (const float*)d_in[2];
    const float* w1    = (const float*)d_in[3];
    const float* w2    = (const float*)d_in[4];
    const float* wa1   = (const float*)d_in[5];
    const float* wa2   = (const float*)d_in[6];
    const float* wu1   = (const float*)d_in[7];
    const float* wu2   = (const float*)d_in[8];
    const float* wr1   = (const float*)d_in[9];
    const float* wr2   = (const float*)d_in[10];
    const float* wr3   = (const float*)d_in[11];
    float* out = (float*)d_out;

    int N = in_sizes[0] / 3;

    LevelP lp;
    double Bv = exp(log(2048.0 / 16.0) / 15.0);
    uint32_t mask = 0;
    for (int l = 0; l < NLEV; l++) {
        double s = 16.0 * pow(Bv, (double)l) - 1.0;
        lp.scale[l] = (float)s;
        long long r = (long long)ceil(s) + 1;
        lp.res[l] = (uint32_t)r;
        if (r * r * r <= (long long)TBL) mask |= (1u << l);
    }
    lp.dense_mask = mask;

    int blocks = (N + 255) / 256;
    ngp_encode_kernel<<<blocks, 256>>>(x, table, w1, w2, wa1, wa2,
                                       wu1, wu2, out, N, lp);
    ngp_render_kernel<<<blocks, 256>>>(d, wr1, wr2, wr3, out, N);
}

// round 8
// speedup vs baseline: 1.0607x; 1.0607x over previous
#include <cuda_runtime.h>
#include <math.h>
#include <stdint.h>

#define NLEV 16
#define TBL (1u << 19)
#define NMAX (1 << 20)

struct LevelP {
    float scale[NLEV];
    uint32_t res[NLEV];
    uint32_t dense_mask;
};

// Planar float4 scratch for h[16] per point: 4 planes x 16 MB = 64 MB.
__device__ float4 g_h0[NMAX];
__device__ float4 g_h1[NMAX];
__device__ float4 g_h2[NMAX];
__device__ float4 g_h3[NMAX];

// ============================ Kernel 1: encode + h + sigma/uncert ==========
__global__ __launch_bounds__(256, 2)
void ngp_encode_kernel(const float* __restrict__ gx,
                       const float* __restrict__ table,
                       const float* __restrict__ w1,
                       const float* __restrict__ w2,
                       const float* __restrict__ wa1,
                       const float* __restrict__ wa2,
                       const float* __restrict__ wu1,
                       const float* __restrict__ wu2,
                       float* __restrict__ out,
                       int N, LevelP lp)
{
    __shared__ __align__(16) float s_w1T[64 * 32];   // [out j][in i]
    __shared__ __align__(16) float s_w2[64 * 16];    // row-major
    __shared__ __align__(16) float s_wa1T[32 * 16];
    __shared__ __align__(16) float s_wa2[32];
    __shared__ __align__(16) float s_wuf[16];        // folded wu1@wu2

    for (int t = threadIdx.x; t < 64 * 32; t += 256) {
        int j = t >> 5, i = t & 31;
        s_w1T[t] = w1[i * 64 + j];
    }
    for (int t = threadIdx.x; t < 64 * 16; t += 256) s_w2[t] = w2[t];
    for (int t = threadIdx.x; t < 32 * 16; t += 256) {
        int j = t >> 4, i = t & 15;
        s_wa1T[t] = wa1[i * 32 + j];
    }
    if (threadIdx.x < 32) s_wa2[threadIdx.x] = wa2[threadIdx.x];
    if (threadIdx.x < 16) {
        float acc = 0.0f;
        for (int j = 0; j < 32; j++)
            acc = fmaf(wu1[threadIdx.x * 32 + j], wu2[j], acc);
        s_wuf[threadIdx.x] = acc;
    }
    __syncthreads();

    int i0 = blockIdx.x * blockDim.x + threadIdx.x;
    if (i0 >= N) return;

    // x01 = (x + 1) * 0.5 -- exact rounded ops (floor-sensitive path)
    float px = __fmul_rn(__fadd_rn(gx[3 * i0 + 0], 1.0f), 0.5f);
    float py = __fmul_rn(__fadd_rn(gx[3 * i0 + 1], 1.0f), 0.5f);
    float pz = __fmul_rn(__fadd_rn(gx[3 * i0 + 2], 1.0f), 0.5f);

    // ---------------- grid encode: 16 levels x 8 corners x float2 ------------
    float enc[32];
    #pragma unroll
    for (int l = 0; l < NLEV; l++) {
        const float s = lp.scale[l];
        const uint32_t res = lp.res[l];
        const bool dense = (lp.dense_mask >> l) & 1u;

        float posx = __fadd_rn(__fmul_rn(px, s), 0.5f);
        float posy = __fadd_rn(__fmul_rn(py, s), 0.5f);
        float posz = __fadd_rn(__fmul_rn(pz, s), 0.5f);
        float gxf = floorf(posx), gyf = floorf(posy), gzf = floorf(posz);
        float fx = posx - gxf, fy = posy - gyf, fz = posz - gzf;
        uint32_t X = (uint32_t)gxf, Y = (uint32_t)gyf, Z = (uint32_t)gzf;

        const float2* tab = (const float2*)table + (size_t)l * TBL;

        uint32_t hy0 = Y * 2654435761u;
        uint32_t hy1 = (Y + 1u) * 2654435761u;
        uint32_t hz0 = Z * 805459861u;
        uint32_t hz1 = (Z + 1u) * 805459861u;
        uint32_t dy0 = Y * res,        dy1 = (Y + 1u) * res;
        uint32_t dz0 = Z * res * res,  dz1 = (Z + 1u) * res * res;

        float wx1 = fx, wx0 = 1.0f - fx;
        float wy1 = fy, wy0 = 1.0f - fy;
        float wz1 = fz, wz0 = 1.0f - fz;

        float e0 = 0.0f, e1 = 0.0f;
        #pragma unroll
        for (int c = 0; c < 8; c++) {
            const uint32_t bi = (c >> 2) & 1, bj = (c >> 1) & 1, bk = c & 1;
            uint32_t cx = X + bi;
            uint32_t idx;
            if (dense) {
                idx = cx + (bj ? dy1 : dy0) + (bk ? dz1 : dz0);
            } else {
                idx = (cx ^ (bj ? hy1 : hy0) ^ (bk ? hz1 : hz0)) & (TBL - 1u);
            }
            float w = (bi ? wx1 : wx0) * (bj ? wy1 : wy0) * (bk ? wz1 : wz0);
            float2 f = __ldg(tab + idx);
            e0 = fmaf(f.x, w, e0);
            e1 = fmaf(f.y, w, e1);
        }
        enc[2 * l + 0] = e0;
        enc[2 * l + 1] = e1;
    }

    // ---------------- h = relu(enc @ w1) @ w2 (streamed) ---------------------
    float h[16];
    #pragma unroll
    for (int k = 0; k < 16; k++) h[k] = 0.0f;
    for (int j = 0; j < 64; j++) {
        const float4* wr = (const float4*)&s_w1T[j * 32];
        float acc = 0.0f;
        #pragma unroll
        for (int q = 0; q < 8; q++) {
            float4 w4 = wr[q];
            acc = fmaf(enc[4 * q + 0], w4.x, acc);
            acc = fmaf(enc[4 * q + 1], w4.y, acc);
            acc = fmaf(enc[4 * q + 2], w4.z, acc);
            acc = fmaf(enc[4 * q + 3], w4.w, acc);
        }
        float t1 = fmaxf(acc, 0.0f);
        const float4* w2r = (const float4*)&s_w2[j * 16];
        #pragma unroll
        for (int q = 0; q < 4; q++) {
            float4 w4 = w2r[q];
            h[4 * q + 0] = fmaf(t1, w4.x, h[4 * q + 0]);
            h[4 * q + 1] = fmaf(t1, w4.y, h[4 * q + 1]);
            h[4 * q + 2] = fmaf(t1, w4.z, h[4 * q + 2]);
            h[4 * q + 3] = fmaf(t1, w4.w, h[4 * q + 3]);
        }
    }

    // ---------------- sigma head: relu(h@wa1)@wa2 ----------------------------
    float sacc = 0.0f;
    for (int j = 0; j < 32; j++) {
        const float4* wa = (const float4*)&s_wa1T[j * 16];
        float a = 0.0f;
        #pragma unroll
        for (int q = 0; q < 4; q++) {
            float4 a4 = wa[q];
            a = fmaf(h[4 * q + 0], a4.x, a);
            a = fmaf(h[4 * q + 1], a4.y, a);
            a = fmaf(h[4 * q + 2], a4.z, a);
            a = fmaf(h[4 * q + 3], a4.w, a);
        }
        sacc = fmaf(fmaxf(a, 0.0f), s_wa2[j], sacc);
    }

    // ---------------- uncert head: h @ folded --------------------------------
    float uacc = 0.0f;
    #pragma unroll
    for (int q = 0; q < 4; q++) {
        float4 w4 = ((const float4*)s_wuf)[q];
        uacc = fmaf(h[4 * q + 0], w4.x, uacc);
        uacc = fmaf(h[4 * q + 1], w4.y, uacc);
        uacc = fmaf(h[4 * q + 2], w4.z, uacc);
        uacc = fmaf(h[4 * q + 3], w4.w, uacc);
    }

    out[i0] = __expf(sacc);
    out[4 * N + i0] = __expf(uacc);

    // ---------------- stage h planar (coalesced float4 stores) ---------------
    g_h0[i0] = make_float4(h[0],  h[1],  h[2],  h[3]);
    g_h1[i0] = make_float4(h[4],  h[5],  h[6],  h[7]);
    g_h2[i0] = make_float4(h[8],  h[9],  h[10], h[11]);
    g_h3[i0] = make_float4(h[12], h[13], h[14], h[15]);
}

// ---------------- spherical harmonics deg 4 ---------------------------------
__device__ __forceinline__ void sh_from_gd(const float* __restrict__ gd, int p,
                                           float* sh)
{
    float vx = __fadd_rn(__fadd_rn(gd[3 * p + 0], 1.0f), -1.0f);
    float vy = __fadd_rn(__fadd_rn(gd[3 * p + 1], 1.0f), -1.0f);
    float vz = __fadd_rn(__fadd_rn(gd[3 * p + 2], 1.0f), -1.0f);
    float x2 = vx * vx, y2 = vy * vy, z2 = vz * vz;
    float xy = vx * vy, yz = vy * vz, xz = vx * vz;
    sh[0]  = 0.28209479177387814f;
    sh[1]  = -0.48860251190291987f * vy;
    sh[2]  = 0.48860251190291987f * vz;
    sh[3]  = -0.48860251190291987f * vx;
    sh[4]  = 1.0925484305920792f * xy;
    sh[5]  = -1.0925484305920792f * yz;
    sh[6]  = 0.94617469575756f * z2 - 0.31539156525252f;
    sh[7]  = -1.0925484305920792f * xz;
    sh[8]  = 0.5462742152960396f * (x2 - y2);
    sh[9]  = 0.5900435899266435f * vy * (-3.0f * x2 + y2);
    sh[10] = 2.890611442640554f * xy * vz;
    sh[11] = 0.4570457994644657f * vy * (1.0f - 5.0f * z2);
    sh[12] = 0.3731763325901154f * vz * (5.0f * z2 - 3.0f);
    sh[13] = 0.4570457994644657f * vx * (1.0f - 5.0f * z2);
    sh[14] = 1.445305721320277f * vz * (x2 - y2);
    sh[15] = 0.5900435899266435f * vx * (-x2 + 3.0f * y2);
}

__device__ __forceinline__ void load_h(int p, float* h)
{
    float4 v;
    v = g_h0[p]; h[0]=v.x;  h[1]=v.y;  h[2]=v.z;  h[3]=v.w;
    v = g_h1[p]; h[4]=v.x;  h[5]=v.y;  h[6]=v.z;  h[7]=v.w;
    v = g_h2[p]; h[8]=v.x;  h[9]=v.y;  h[10]=v.z; h[11]=v.w;
    v = g_h3[p]; h[12]=v.x; h[13]=v.y; h[14]=v.z; h[15]=v.w;
}

// ============================ Kernel 2: dual-point render ===================
__global__ __launch_bounds__(128, 2)
void ngp_render_kernel(const float* __restrict__ gd,
                       const float* __restrict__ wr1,
                       const float* __restrict__ wr2,
                       const float* __restrict__ wr3,
                       float* __restrict__ out,
                       int N)
{
    __shared__ __align__(16) float s_wr1T[64 * 32];
    __shared__ __align__(16) float s_wr2T[64 * 64];
    __shared__ __align__(16) float s_wr3p[64 * 4];   // padded -> LDS.128

    const int tid = threadIdx.x;
    for (int t = tid; t < 64 * 32; t += 128) {
        int j = t >> 5, i = t & 31;
        s_wr1T[t] = wr1[i * 64 + j];
    }
    for (int t = tid; t < 64 * 64; t += 128) {
        int j = t >> 6, i = t & 63;
        s_wr2T[t] = wr2[i * 64 + j];
    }
    for (int t = tid; t < 64; t += 128) {
        s_wr3p[t * 4 + 0] = wr3[t * 3 + 0];
        s_wr3p[t * 4 + 1] = wr3[t * 3 + 1];
        s_wr3p[t * 4 + 2] = wr3[t * 3 + 2];
        s_wr3p[t * 4 + 3] = 0.0f;
    }
    __syncthreads();

    const int p0 = blockIdx.x * 256 + tid;
    if (p0 >= N) return;
    int p1 = p0 + 128;
    const bool has1 = (p1 < N);
    if (!has1) p1 = p0;

    float h0[16], h1[16];
    load_h(p0, h0);
    load_h(p1, h1);

    float sh0[16], sh1[16];
    sh_from_gd(gd, p0, sh0);
    sh_from_gd(gd, p1, sh1);

    // -------- z1 = relu([sh, h] @ wr1) (dual) --------------------------------
    float z1a[64], z1b[64];
    #pragma unroll 2
    for (int j = 0; j < 64; j++) {
        const float4* wr = (const float4*)&s_wr1T[j * 32];
        float a0 = 0.0f, a1 = 0.0f;
        #pragma unroll
        for (int q = 0; q < 4; q++) {
            float4 w4 = wr[q];
            a0 = fmaf(sh0[4 * q + 0], w4.x, a0);
            a0 = fmaf(sh0[4 * q + 1], w4.y, a0);
            a0 = fmaf(sh0[4 * q + 2], w4.z, a0);
            a0 = fmaf(sh0[4 * q + 3], w4.w, a0);
            a1 = fmaf(sh1[4 * q + 0], w4.x, a1);
            a1 = fmaf(sh1[4 * q + 1], w4.y, a1);
            a1 = fmaf(sh1[4 * q + 2], w4.z, a1);
            a1 = fmaf(sh1[4 * q + 3], w4.w, a1);
        }
        #pragma unroll
        for (int q = 0; q < 4; q++) {
            float4 w4 = wr[4 + q];
            a0 = fmaf(h0[4 * q + 0], w4.x, a0);
            a0 = fmaf(h0[4 * q + 1], w4.y, a0);
            a0 = fmaf(h0[4 * q + 2], w4.z, a0);
            a0 = fmaf(h0[4 * q + 3], w4.w, a0);
            a1 = fmaf(h1[4 * q + 0], w4.x, a1);
            a1 = fmaf(h1[4 * q + 1], w4.y, a1);
            a1 = fmaf(h1[4 * q + 2], w4.z, a1);
            a1 = fmaf(h1[4 * q + 3], w4.w, a1);
        }
        z1a[j] = fmaxf(a0, 0.0f);
        z1b[j] = fmaxf(a1, 0.0f);
    }

    // -------- rgb = sigmoid(relu(z1 @ wr2) @ wr3) (dual) ---------------------
    float r00 = 0.0f, r01 = 0.0f, r02 = 0.0f;
    float r10 = 0.0f, r11 = 0.0f, r12 = 0.0f;
    for (int j = 0; j < 64; j++) {
        const float4* wr = (const float4*)&s_wr2T[j * 64];
        float a0 = 0.0f, a1 = 0.0f;
        #pragma unroll
        for (int q = 0; q < 16; q++) {
            float4 w4 = wr[q];
            a0 = fmaf(z1a[4 * q + 0], w4.x, a0);
            a0 = fmaf(z1a[4 * q + 1], w4.y, a0);
            a0 = fmaf(z1a[4 * q + 2], w4.z, a0);
            a0 = fmaf(z1a[4 * q + 3], w4.w, a0);
            a1 = fmaf(z1b[4 * q + 0], w4.x, a1);
            a1 = fmaf(z1b[4 * q + 1], w4.y, a1);
            a1 = fmaf(z1b[4 * q + 2], w4.z, a1);
            a1 = fmaf(z1b[4 * q + 3], w4.w, a1);
        }
        float za = fmaxf(a0, 0.0f), zb = fmaxf(a1, 0.0f);
        float4 w3 = ((const float4*)s_wr3p)[j];
        r00 = fmaf(za, w3.x, r00);
        r01 = fmaf(za, w3.y, r01);
        r02 = fmaf(za, w3.z, r02);
        r10 = fmaf(zb, w3.x, r10);
        r11 = fmaf(zb, w3.y, r11);
        r12 = fmaf(zb, w3.z, r12);
    }

    out[N + 3 * p0 + 0] = __fdividef(1.0f, 1.0f + __expf(-r00));
    out[N + 3 * p0 + 1] = __fdividef(1.0f, 1.0f + __expf(-r01));
    out[N + 3 * p0 + 2] = __fdividef(1.0f, 1.0f + __expf(-r02));
    if (has1) {
        out[N + 3 * p1 + 0] = __fdividef(1.0f, 1.0f + __expf(-r10));
        out[N + 3 * p1 + 1] = __fdividef(1.0f, 1.0f + __expf(-r11));
        out[N + 3 * p1 + 2] = __fdividef(1.0f, 1.0f + __expf(-r12));
    }
}

extern "C" void kernel_launch(void* const* d_in, const int* in_sizes, int n_in,
                              void* d_out, int out_size) {
    const float* x     = (const float*)d_in[0];
    const float* d     = (const float*)d_in[1];
    const float* table = (const float*)d_in[2];
    const float* w1    = (const float*)d_in[3];
    const float* w2    = (const float*)d_in[4];
    const float* wa1   = (const float*)d_in[5];
    const float* wa2   = (const float*)d_in[6];
    const float* wu1   = (const float*)d_in[7];
    const float* wu2   = (const float*)d_in[8];
    const float* wr1   = (const float*)d_in[9];
    const float* wr2   = (const float*)d_in[10];
    const float* wr3   = (const float*)d_in[11];
    float* out = (float*)d_out;

    int N = in_sizes[0] / 3;

    LevelP lp;
    double Bv = exp(log(2048.0 / 16.0) / 15.0);
    uint32_t mask = 0;
    for (int l = 0; l < NLEV; l++) {
        double s = 16.0 * pow(Bv, (double)l) - 1.0;
        lp.scale[l] = (float)s;
        long long r = (long long)ceil(s) + 1;
        lp.res[l] = (uint32_t)r;
        if (r * r * r <= (long long)TBL) mask |= (1u << l);
    }
    lp.dense_mask = mask;

    int blocks = (N + 255) / 256;
    ngp_encode_kernel<<<blocks, 256>>>(x, table, w1, w2, wa1, wa2,
                                       wu1, wu2, out, N, lp);
    ngp_render_kernel<<<blocks, 128>>>(d, wr1, wr2, wr3, out, N);
}

// round 9
// speedup vs baseline: 1.1518x; 1.0858x over previous
#include <cuda_runtime.h>
#include <math.h>
#include <stdint.h>

#define NLEV 16
#define TBL (1u << 19)
#define NMAX (1 << 20)

struct LevelP {
    float scale[NLEV];
    uint32_t res[NLEV];
    uint32_t dense_mask;
};

// Planar float4 scratch for h[16] per point: 4 planes x 16 MB = 64 MB.
__device__ float4 g_h0[NMAX];
__device__ float4 g_h1[NMAX];
__device__ float4 g_h2[NMAX];
__device__ float4 g_h3[NMAX];

// ---------------- grid encode for one point (enc stays in regs) -------------
__device__ __forceinline__ void grid_encode_pt(float px, float py, float pz,
                                               const float* __restrict__ table,
                                               const LevelP& lp, float* enc)
{
    #pragma unroll
    for (int l = 0; l < NLEV; l++) {
        const float s = lp.scale[l];
        const uint32_t res = lp.res[l];
        const bool dense = (lp.dense_mask >> l) & 1u;

        // pos = x01 * s + 0.5 exact (floor-sensitive path)
        float posx = __fadd_rn(__fmul_rn(px, s), 0.5f);
        float posy = __fadd_rn(__fmul_rn(py, s), 0.5f);
        float posz = __fadd_rn(__fmul_rn(pz, s), 0.5f);
        float gxf = floorf(posx), gyf = floorf(posy), gzf = floorf(posz);
        float fx = posx - gxf, fy = posy - gyf, fz = posz - gzf;
        uint32_t X = (uint32_t)gxf, Y = (uint32_t)gyf, Z = (uint32_t)gzf;

        const float2* tab = (const float2*)table + (size_t)l * TBL;

        uint32_t hy0 = Y * 2654435761u;
        uint32_t hy1 = (Y + 1u) * 2654435761u;
        uint32_t hz0 = Z * 805459861u;
        uint32_t hz1 = (Z + 1u) * 805459861u;
        uint32_t dy0 = Y * res,        dy1 = (Y + 1u) * res;
        uint32_t dz0 = Z * res * res,  dz1 = (Z + 1u) * res * res;

        float wx1 = fx, wx0 = 1.0f - fx;
        float wy1 = fy, wy0 = 1.0f - fy;
        float wz1 = fz, wz0 = 1.0f - fz;

        float e0 = 0.0f, e1 = 0.0f;
        #pragma unroll
        for (int c = 0; c < 8; c++) {
            const uint32_t bi = (c >> 2) & 1, bj = (c >> 1) & 1, bk = c & 1;
            uint32_t cx = X + bi;
            uint32_t idx;
            if (dense) {
                idx = cx + (bj ? dy1 : dy0) + (bk ? dz1 : dz0);
            } else {
                idx = (cx ^ (bj ? hy1 : hy0) ^ (bk ? hz1 : hz0)) & (TBL - 1u);
            }
            float w = (bi ? wx1 : wx0) * (bj ? wy1 : wy0) * (bk ? wz1 : wz0);
            float2 f = __ldg(tab + idx);
            e0 = fmaf(f.x, w, e0);
            e1 = fmaf(f.y, w, e1);
        }
        enc[2 * l + 0] = e0;
        enc[2 * l + 1] = e1;
    }
}

// ============================ Kernel 1: dual-point encode ===================
__global__ __launch_bounds__(128, 2)
void ngp_encode_kernel(const float* __restrict__ gx,
                       const float* __restrict__ table,
                       const float* __restrict__ w1,
                       const float* __restrict__ w2,
                       const float* __restrict__ wa1,
                       const float* __restrict__ wa2,
                       const float* __restrict__ wu1,
                       const float* __restrict__ wu2,
                       float* __restrict__ out,
                       int N, LevelP lp)
{
    __shared__ __align__(16) float s_w1T[64 * 32];   // [out j][in i]
    __shared__ __align__(16) float s_w2[64 * 16];    // row-major
    __shared__ __align__(16) float s_wa1T[32 * 16];
    __shared__ __align__(16) float s_wa2[32];
    __shared__ __align__(16) float s_wuf[16];        // folded wu1@wu2

    const int tid = threadIdx.x;
    for (int t = tid; t < 64 * 32; t += 128) {
        int j = t >> 5, i = t & 31;
        s_w1T[t] = w1[i * 64 + j];
    }
    for (int t = tid; t < 64 * 16; t += 128) s_w2[t] = w2[t];
    for (int t = tid; t < 32 * 16; t += 128) {
        int j = t >> 4, i = t & 15;
        s_wa1T[t] = wa1[i * 32 + j];
    }
    if (tid < 32) s_wa2[tid] = wa2[tid];
    if (tid < 16) {
        float acc = 0.0f;
        for (int j = 0; j < 32; j++) acc = fmaf(wu1[tid * 32 + j], wu2[j], acc);
        s_wuf[tid] = acc;
    }
    __syncthreads();

    const int p0 = blockIdx.x * 256 + tid;
    if (p0 >= N) return;
    int p1 = p0 + 128;
    const bool has1 = (p1 < N);
    if (!has1) p1 = p0;

    // x01 = (x + 1) * 0.5 exact
    float px0 = __fmul_rn(__fadd_rn(gx[3 * p0 + 0], 1.0f), 0.5f);
    float py0 = __fmul_rn(__fadd_rn(gx[3 * p0 + 1], 1.0f), 0.5f);
    float pz0 = __fmul_rn(__fadd_rn(gx[3 * p0 + 2], 1.0f), 0.5f);
    float px1 = __fmul_rn(__fadd_rn(gx[3 * p1 + 0], 1.0f), 0.5f);
    float py1 = __fmul_rn(__fadd_rn(gx[3 * p1 + 1], 1.0f), 0.5f);
    float pz1 = __fmul_rn(__fadd_rn(gx[3 * p1 + 2], 1.0f), 0.5f);

    float enc0[32], enc1[32];
    grid_encode_pt(px0, py0, pz0, table, lp, enc0);
    grid_encode_pt(px1, py1, pz1, table, lp, enc1);

    // -------- h = relu(enc @ w1) @ w2 : each weight load feeds both points --
    float h0[16], h1[16];
    #pragma unroll
    for (int k = 0; k < 16; k++) { h0[k] = 0.0f; h1[k] = 0.0f; }
    #pragma unroll 2
    for (int j = 0; j < 64; j++) {
        const float4* wr = (const float4*)&s_w1T[j * 32];
        float a0 = 0.0f, a1 = 0.0f;
        #pragma unroll
        for (int q = 0; q < 8; q++) {
            float4 w4 = wr[q];
            a0 = fmaf(enc0[4 * q + 0], w4.x, a0);
            a0 = fmaf(enc0[4 * q + 1], w4.y, a0);
            a0 = fmaf(enc0[4 * q + 2], w4.z, a0);
            a0 = fmaf(enc0[4 * q + 3], w4.w, a0);
            a1 = fmaf(enc1[4 * q + 0], w4.x, a1);
            a1 = fmaf(enc1[4 * q + 1], w4.y, a1);
            a1 = fmaf(enc1[4 * q + 2], w4.z, a1);
            a1 = fmaf(enc1[4 * q + 3], w4.w, a1);
        }
        float t0 = fmaxf(a0, 0.0f), t1 = fmaxf(a1, 0.0f);
        const float4* w2r = (const float4*)&s_w2[j * 16];
        #pragma unroll
        for (int q = 0; q < 4; q++) {
            float4 w4 = w2r[q];
            h0[4 * q + 0] = fmaf(t0, w4.x, h0[4 * q + 0]);
            h0[4 * q + 1] = fmaf(t0, w4.y, h0[4 * q + 1]);
            h0[4 * q + 2] = fmaf(t0, w4.z, h0[4 * q + 2]);
            h0[4 * q + 3] = fmaf(t0, w4.w, h0[4 * q + 3]);
            h1[4 * q + 0] = fmaf(t1, w4.x, h1[4 * q + 0]);
            h1[4 * q + 1] = fmaf(t1, w4.y, h1[4 * q + 1]);
            h1[4 * q + 2] = fmaf(t1, w4.z, h1[4 * q + 2]);
            h1[4 * q + 3] = fmaf(t1, w4.w, h1[4 * q + 3]);
        }
    }

    // -------- sigma head (dual, shared weights) ------------------------------
    float sacc0 = 0.0f, sacc1 = 0.0f;
    #pragma unroll 4
    for (int j = 0; j < 32; j++) {
        const float4* wa = (const float4*)&s_wa1T[j * 16];
        float a0 = 0.0f, a1 = 0.0f;
        #pragma unroll
        for (int q = 0; q < 4; q++) {
            float4 w4 = wa[q];
            a0 = fmaf(h0[4 * q + 0], w4.x, a0);
            a0 = fmaf(h0[4 * q + 1], w4.y, a0);
            a0 = fmaf(h0[4 * q + 2], w4.z, a0);
            a0 = fmaf(h0[4 * q + 3], w4.w, a0);
            a1 = fmaf(h1[4 * q + 0], w4.x, a1);
            a1 = fmaf(h1[4 * q + 1], w4.y, a1);
            a1 = fmaf(h1[4 * q + 2], w4.z, a1);
            a1 = fmaf(h1[4 * q + 3], w4.w, a1);
        }
        float w = s_wa2[j];
        sacc0 = fmaf(fmaxf(a0, 0.0f), w, sacc0);
        sacc1 = fmaf(fmaxf(a1, 0.0f), w, sacc1);
    }

    // -------- uncert head (folded, dual) -------------------------------------
    float uacc0 = 0.0f, uacc1 = 0.0f;
    #pragma unroll
    for (int q = 0; q < 4; q++) {
        float4 w4 = ((const float4*)s_wuf)[q];
        uacc0 = fmaf(h0[4 * q + 0], w4.x, uacc0);
        uacc0 = fmaf(h0[4 * q + 1], w4.y, uacc0);
        uacc0 = fmaf(h0[4 * q + 2], w4.z, uacc0);
        uacc0 = fmaf(h0[4 * q + 3], w4.w, uacc0);
        uacc1 = fmaf(h1[4 * q + 0], w4.x, uacc1);
        uacc1 = fmaf(h1[4 * q + 1], w4.y, uacc1);
        uacc1 = fmaf(h1[4 * q + 2], w4.z, uacc1);
        uacc1 = fmaf(h1[4 * q + 3], w4.w, uacc1);
    }

    out[p0] = __expf(sacc0);
    out[4 * N + p0] = __expf(uacc0);
    g_h0[p0] = make_float4(h0[0],  h0[1],  h0[2],  h0[3]);
    g_h1[p0] = make_float4(h0[4],  h0[5],  h0[6],  h0[7]);
    g_h2[p0] = make_float4(h0[8],  h0[9],  h0[10], h0[11]);
    g_h3[p0] = make_float4(h0[12], h0[13], h0[14], h0[15]);
    if (has1) {
        out[p1] = __expf(sacc1);
        out[4 * N + p1] = __expf(uacc1);
        g_h0[p1] = make_float4(h1[0],  h1[1],  h1[2],  h1[3]);
        g_h1[p1] = make_float4(h1[4],  h1[5],  h1[6],  h1[7]);
        g_h2[p1] = make_float4(h1[8],  h1[9],  h1[10], h1[11]);
        g_h3[p1] = make_float4(h1[12], h1[13], h1[14], h1[15]);
    }
}

// ---------------- spherical harmonics deg 4 ---------------------------------
__device__ __forceinline__ void sh_from_gd(const float* __restrict__ gd, int p,
                                           float* sh)
{
    float vx = __fadd_rn(__fadd_rn(gd[3 * p + 0], 1.0f), -1.0f);
    float vy = __fadd_rn(__fadd_rn(gd[3 * p + 1], 1.0f), -1.0f);
    float vz = __fadd_rn(__fadd_rn(gd[3 * p + 2], 1.0f), -1.0f);
    float x2 = vx * vx, y2 = vy * vy, z2 = vz * vz;
    float xy = vx * vy, yz = vy * vz, xz = vx * vz;
    sh[0]  = 0.28209479177387814f;
    sh[1]  = -0.48860251190291987f * vy;
    sh[2]  = 0.48860251190291987f * vz;
    sh[3]  = -0.48860251190291987f * vx;
    sh[4]  = 1.0925484305920792f * xy;
    sh[5]  = -1.0925484305920792f * yz;
    sh[6]  = 0.94617469575756f * z2 - 0.31539156525252f;
    sh[7]  = -1.0925484305920792f * xz;
    sh[8]  = 0.5462742152960396f * (x2 - y2);
    sh[9]  = 0.5900435899266435f * vy * (-3.0f * x2 + y2);
    sh[10] = 2.890611442640554f * xy * vz;
    sh[11] = 0.4570457994644657f * vy * (1.0f - 5.0f * z2);
    sh[12] = 0.3731763325901154f * vz * (5.0f * z2 - 3.0f);
    sh[13] = 0.4570457994644657f * vx * (1.0f - 5.0f * z2);
    sh[14] = 1.445305721320277f * vz * (x2 - y2);
    sh[15] = 0.5900435899266435f * vx * (-x2 + 3.0f * y2);
}

__device__ __forceinline__ void load_h(int p, float* h)
{
    float4 v;
    v = g_h0[p]; h[0]=v.x;  h[1]=v.y;  h[2]=v.z;  h[3]=v.w;
    v = g_h1[p]; h[4]=v.x;  h[5]=v.y;  h[6]=v.z;  h[7]=v.w;
    v = g_h2[p]; h[8]=v.x;  h[9]=v.y;  h[10]=v.z; h[11]=v.w;
    v = g_h3[p]; h[12]=v.x; h[13]=v.y; h[14]=v.z; h[15]=v.w;
}

// ============================ Kernel 2: dual-point render ===================
__global__ __launch_bounds__(128, 2)
void ngp_render_kernel(const float* __restrict__ gd,
                       const float* __restrict__ wr1,
                       const float* __restrict__ wr2,
                       const float* __restrict__ wr3,
                       float* __restrict__ out,
                       int N)
{
    __shared__ __align__(16) float s_wr1T[64 * 32];
    __shared__ __align__(16) float s_wr2T[64 * 64];
    __shared__ __align__(16) float s_wr3p[64 * 4];   // padded -> LDS.128

    const int tid = threadIdx.x;
    for (int t = tid; t < 64 * 32; t += 128) {
        int j = t >> 5, i = t & 31;
        s_wr1T[t] = wr1[i * 64 + j];
    }
    for (int t = tid; t < 64 * 64; t += 128) {
        int j = t >> 6, i = t & 63;
        s_wr2T[t] = wr2[i * 64 + j];
    }
    for (int t = tid; t < 64; t += 128) {
        s_wr3p[t * 4 + 0] = wr3[t * 3 + 0];
        s_wr3p[t * 4 + 1] = wr3[t * 3 + 1];
        s_wr3p[t * 4 + 2] = wr3[t * 3 + 2];
        s_wr3p[t * 4 + 3] = 0.0f;
    }
    __syncthreads();

    const int p0 = blockIdx.x * 256 + tid;
    if (p0 >= N) return;
    int p1 = p0 + 128;
    const bool has1 = (p1 < N);
    if (!has1) p1 = p0;

    float h0[16], h1[16];
    load_h(p0, h0);
    load_h(p1, h1);

    float sh0[16], sh1[16];
    sh_from_gd(gd, p0, sh0);
    sh_from_gd(gd, p1, sh1);

    // -------- z1 = relu([sh, h] @ wr1) (dual) --------------------------------
    float z1a[64], z1b[64];
    #pragma unroll 2
    for (int j = 0; j < 64; j++) {
        const float4* wr = (const float4*)&s_wr1T[j * 32];
        float a0 = 0.0f, a1 = 0.0f;
        #pragma unroll
        for (int q = 0; q < 4; q++) {
            float4 w4 = wr[q];
            a0 = fmaf(sh0[4 * q + 0], w4.x, a0);
            a0 = fmaf(sh0[4 * q + 1], w4.y, a0);
            a0 = fmaf(sh0[4 * q + 2], w4.z, a0);
            a0 = fmaf(sh0[4 * q + 3], w4.w, a0);
            a1 = fmaf(sh1[4 * q + 0], w4.x, a1);
            a1 = fmaf(sh1[4 * q + 1], w4.y, a1);
            a1 = fmaf(sh1[4 * q + 2], w4.z, a1);
            a1 = fmaf(sh1[4 * q + 3], w4.w, a1);
        }
        #pragma unroll
        for (int q = 0; q < 4; q++) {
            float4 w4 = wr[4 + q];
            a0 = fmaf(h0[4 * q + 0], w4.x, a0);
            a0 = fmaf(h0[4 * q + 1], w4.y, a0);
            a0 = fmaf(h0[4 * q + 2], w4.z, a0);
            a0 = fmaf(h0[4 * q + 3], w4.w, a0);
            a1 = fmaf(h1[4 * q + 0], w4.x, a1);
            a1 = fmaf(h1[4 * q + 1], w4.y, a1);
            a1 = fmaf(h1[4 * q + 2], w4.z, a1);
            a1 = fmaf(h1[4 * q + 3], w4.w, a1);
        }
        z1a[j] = fmaxf(a0, 0.0f);
        z1b[j] = fmaxf(a1, 0.0f);
    }

    // -------- rgb = sigmoid(relu(z1 @ wr2) @ wr3) (dual) ---------------------
    float r00 = 0.0f, r01 = 0.0f, r02 = 0.0f;
    float r10 = 0.0f, r11 = 0.0f, r12 = 0.0f;
    for (int j = 0; j < 64; j++) {
        const float4* wr = (const float4*)&s_wr2T[j * 64];
        float a0 = 0.0f, a1 = 0.0f;
        #pragma unroll
        for (int q = 0; q < 16; q++) {
            float4 w4 = wr[q];
            a0 = fmaf(z1a[4 * q + 0], w4.x, a0);
            a0 = fmaf(z1a[4 * q + 1], w4.y, a0);
            a0 = fmaf(z1a[4 * q + 2], w4.z, a0);
            a0 = fmaf(z1a[4 * q + 3], w4.w, a0);
            a1 = fmaf(z1b[4 * q + 0], w4.x, a1);
            a1 = fmaf(z1b[4 * q + 1], w4.y, a1);
            a1 = fmaf(z1b[4 * q + 2], w4.z, a1);
            a1 = fmaf(z1b[4 * q + 3], w4.w, a1);
        }
        float za = fmaxf(a0, 0.0f), zb = fmaxf(a1, 0.0f);
        float4 w3 = ((const float4*)s_wr3p)[j];
        r00 = fmaf(za, w3.x, r00);
        r01 = fmaf(za, w3.y, r01);
        r02 = fmaf(za, w3.z, r02);
        r10 = fmaf(zb, w3.x, r10);
        r11 = fmaf(zb, w3.y, r11);
        r12 = fmaf(zb, w3.z, r12);
    }

    out[N + 3 * p0 + 0] = __fdividef(1.0f, 1.0f + __expf(-r00));
    out[N + 3 * p0 + 1] = __fdividef(1.0f, 1.0f + __expf(-r01));
    out[N + 3 * p0 + 2] = __fdividef(1.0f, 1.0f + __expf(-r02));
    if (has1) {
        out[N + 3 * p1 + 0] = __fdividef(1.0f, 1.0f + __expf(-r10));
        out[N + 3 * p1 + 1] = __fdividef(1.0f, 1.0f + __expf(-r11));
        out[N + 3 * p1 + 2] = __fdividef(1.0f, 1.0f + __expf(-r12));
    }
}

extern "C" void kernel_launch(void* const* d_in, const int* in_sizes, int n_in,
                              void* d_out, int out_size) {
    const float* x     = (const float*)d_in[0];
    const float* d     = (const float*)d_in[1];
    const float* table = (const float*)d_in[2];
    const float* w1    = (const float*)d_in[3];
    const float* w2    = (const float*)d_in[4];
    const float* wa1   = (const float*)d_in[5];
    const float* wa2   = (const float*)d_in[6];
    const float* wu1   = (const float*)d_in[7];
    const float* wu2   = (const float*)d_in[8];
    const float* wr1   = (const float*)d_in[9];
    const float* wr2   = (const float*)d_in[10];
    const float* wr3   = (const float*)d_in[11];
    float* out = (float*)d_out;

    int N = in_sizes[0] / 3;

    LevelP lp;
    double Bv = exp(log(2048.0 / 16.0) / 15.0);
    uint32_t mask = 0;
    for (int l = 0; l < NLEV; l++) {
        double s = 16.0 * pow(Bv, (double)l) - 1.0;
        lp.scale[l] = (float)s;
        long long r = (long long)ceil(s) + 1;
        lp.res[l] = (uint32_t)r;
        if (r * r * r <= (long long)TBL) mask |= (1u << l);
    }
    lp.dense_mask = mask;

    int blocks = (N + 255) / 256;
    ngp_encode_kernel<<<blocks, 128>>>(x, table, w1, w2, wa1, wa2,
                                       wu1, wu2, out, N, lp);
    ngp_render_kernel<<<blocks, 128>>>(d, wr1, wr2, wr3, out, N);
}